// round 1
// baseline (speedup 1.0000x reference)
#include <cuda_runtime.h>

#define NXMAX (1 << 20)
#define BLK 256
#define NSTEPS 32

// Double-buffered conserved state (static scratch; no runtime allocation).
__device__ float g_r[2][NXMAX];
__device__ float g_m[2][NXMAX];
__device__ float g_e[2][NXMAX];
// Max wavespeed per step, ping-pong slots. Positive floats compare correctly as uints.
__device__ unsigned int g_maxbits[2];
__device__ float g_t;
__device__ float g_dtdx;

__global__ void pre_kernel() {
    g_maxbits[0] = 0u;
    g_t = 0.0f;
}

__device__ __forceinline__ void block_max_atomic(float spd, unsigned int* target) {
    unsigned int bits = __float_as_uint(spd);
    bits = __reduce_max_sync(0xffffffffu, bits);
    __shared__ unsigned int swm[BLK / 32];
    int tid = threadIdx.x;
    if ((tid & 31) == 0) swm[tid >> 5] = bits;
    __syncthreads();
    if (tid == 0) {
        unsigned int m = swm[0];
#pragma unroll
        for (int w = 1; w < BLK / 32; w++) m = max(m, swm[w]);
        atomicMax(target, m);
    }
}

// Convert primitives -> conserved, reduce initial max wavespeed into slot 0.
__global__ void init_kernel(const float* __restrict__ rho, const float* __restrict__ u,
                            const float* __restrict__ p, int n) {
    int i = blockIdx.x * BLK + threadIdx.x;
    float spd = 0.0f;
    if (i < n) {
        float r = rho[i], uu = u[i], pp = p[i];
        float m = r * uu;
        g_r[0][i] = r;
        g_m[0][i] = m;
        g_e[0][i] = pp * 2.5f + 0.5f * m * uu;
        spd = fabsf(uu) + sqrtf(__fdividef(1.4f * pp, r));
    }
    block_max_atomic(spd, &g_maxbits[0]);
}

// dt for this step from slot `cur`; zero the other slot for the fused reduction
// performed by this step's flux kernel.
__global__ void dt_kernel(const float* __restrict__ tf, int cur) {
    float mx = __uint_as_float(g_maxbits[cur]);
    float dt = 5e-4f / mx;                 // CFL * DX / max
    float rem = fmaxf(*tf - g_t, 0.0f);
    dt = fminf(dt, rem);
    g_t += dt;
    g_dtdx = dt / 1e-3f;
    g_maxbits[cur ^ 1] = 0u;
}

// One Euler step: tile of BLK cells + 2 halo cells in shared, one Roe flux per
// interface (BLK+1), conserved update, fused max-|u|+c reduction of NEW state.
// LAST step writes primitives (rho,u,p) to prim_out instead of conserved buffers.
template <bool LAST>
__global__ void flux_kernel(int src, float* __restrict__ prim_out, int n) {
    const float* __restrict__ r_in = g_r[src];
    const float* __restrict__ m_in = g_m[src];
    const float* __restrict__ e_in = g_e[src];
    float* __restrict__ r_out = g_r[src ^ 1];
    float* __restrict__ m_out = g_m[src ^ 1];
    float* __restrict__ e_out = g_e[src ^ 1];

    __shared__ float s_r[BLK + 2], s_m[BLK + 2], s_E[BLK + 2];
    __shared__ float s_u[BLK + 2], s_p[BLK + 2], s_q[BLK + 2], s_H[BLK + 2];
    __shared__ float s_Fr[BLK + 1], s_Fm[BLK + 1], s_Fe[BLK + 1];

    const int tid = threadIdx.x;
    const int base = blockIdx.x * BLK;

    // Load cells base-1 .. base+BLK (edge-replicated ghost cells) and derive
    // per-cell quantities once.
    for (int k = tid; k < BLK + 2; k += BLK) {
        int c = base - 1 + k;
        c = max(0, min(c, n - 1));
        float r = r_in[c], m = m_in[c], E = e_in[c];
        float ir = __fdividef(1.0f, r);
        float uu = m * ir;
        float pp = 0.4f * (E - 0.5f * m * uu);
        s_r[k] = r;
        s_m[k] = m;
        s_E[k] = E;
        s_u[k] = uu;
        s_p[k] = pp;
        s_q[k] = sqrtf(r);
        s_H[k] = (E + pp) * ir;
    }
    __syncthreads();

    // BLK+1 interface fluxes (Roe with Harten entropy fix).
    for (int j = tid; j < BLK + 1; j += BLK) {
        float rL = s_r[j],     rR = s_r[j + 1];
        float uL = s_u[j],     uR = s_u[j + 1];
        float pL = s_p[j],     pR = s_p[j + 1];
        float qL = s_q[j],     qR = s_q[j + 1];
        float HL = s_H[j],     HR = s_H[j + 1];
        float mL = s_m[j],     mR = s_m[j + 1];
        float EL = s_E[j],     ER = s_E[j + 1];

        float rd = __fdividef(1.0f, qL + qR);
        float ur = (qL * uL + qR * uR) * rd;
        float Hr = (qL * HL + qR * HR) * rd;
        float c2 = fmaxf(0.4f * (Hr - 0.5f * ur * ur), 1e-10f);
        float c = sqrtf(c2);
        float e2 = 0.01f * c2;               // (0.1*c)^2
        float l1 = ur - c, l3 = ur + c;
        float a1 = sqrtf(l1 * l1 + e2);
        float a2 = sqrtf(ur * ur + e2);
        float a3 = sqrtf(l3 * l3 + e2);

        float drho = rR - rL, du = uR - uL, dp = pR - pL;
        float ic2 = __fdividef(1.0f, c2);
        float h = 0.5f * ic2;
        float al2 = drho - dp * ic2;
        float crdu = c * rR * du;
        float b1 = a1 * ((dp - crdu) * h);
        float b3 = a3 * ((dp + crdu) * h);
        float b2 = a2 * al2;

        float dr = b1 + b2 + b3;
        float dm = b1 * l1 + b2 * ur + b3 * l3;
        float uc = ur * c;
        float de = b1 * (Hr - uc) + b2 * (0.5f * ur * ur) + b3 * (Hr + uc);

        float FmL = mL * uL + pL, FmR = mR * uR + pR;
        float FeL = uL * (EL + pL), FeR = uR * (ER + pR);

        s_Fr[j] = 0.5f * (mL + mR - dr);
        s_Fm[j] = 0.5f * (FmL + FmR - dm);
        s_Fe[j] = 0.5f * (FeL + FeR - de);
    }
    __syncthreads();

    const int i = base + tid;
    const float dtdx = g_dtdx;
    const int k = tid + 1;
    float nr = s_r[k] - dtdx * (s_Fr[tid + 1] - s_Fr[tid]);
    float nm = s_m[k] - dtdx * (s_Fm[tid + 1] - s_Fm[tid]);
    float ne = s_E[k] - dtdx * (s_Fe[tid + 1] - s_Fe[tid]);
    float inr = __fdividef(1.0f, nr);
    float nu = nm * inr;
    float np = 0.4f * (ne - 0.5f * nm * nu);

    if (LAST) {
        if (i < n) {
            prim_out[i] = nr;
            prim_out[n + i] = nu;
            prim_out[2 * n + i] = np;
        }
    } else {
        float spd = 0.0f;
        if (i < n) {
            r_out[i] = nr;
            m_out[i] = nm;
            e_out[i] = ne;
            spd = fabsf(nu) + sqrtf(1.4f * np * inr);
        }
        block_max_atomic(spd, &g_maxbits[src ^ 1]);
    }
}

extern "C" void kernel_launch(void* const* d_in, const int* in_sizes, int n_in,
                              void* d_out, int out_size) {
    const float* rho = (const float*)d_in[0];
    const float* u = (const float*)d_in[1];
    const float* p = (const float*)d_in[2];
    const float* tf = (const float*)d_in[3];
    float* out = (float*)d_out;
    int n = in_sizes[0];
    if (n > NXMAX) return;
    int nblk = (n + BLK - 1) / BLK;

    pre_kernel<<<1, 1>>>();
    init_kernel<<<nblk, BLK>>>(rho, u, p, n);
    for (int s = 0; s < NSTEPS; s++) {
        dt_kernel<<<1, 1>>>(tf, s & 1);
        if (s < NSTEPS - 1)
            flux_kernel<false><<<nblk, BLK>>>(s & 1, nullptr, n);
        else
            flux_kernel<true><<<nblk, BLK>>>(s & 1, out, n);
    }
}

// round 2
// speedup vs baseline: 1.7511x; 1.7511x over previous
#include <cuda_runtime.h>

#define NXMAX (1 << 20)
#define BLK 256
#define NSTEPS 32

// Double-buffered conserved state (static scratch; no runtime allocation).
__device__ float g_r[2][NXMAX];
__device__ float g_m[2][NXMAX];
__device__ float g_e[2][NXMAX];
__device__ unsigned int g_maxbits;   // running max of |u|+c (positive float bits)
__device__ unsigned int g_count;     // last-block-finish counter
__device__ float g_t;
__device__ float g_dtdx;

__global__ void pre_kernel() {
    g_maxbits = 0u;
    g_count = 0u;
    g_t = 0.0f;
}

// Fast sqrt via single MUFU.RSQ (args are strictly positive here).
__device__ __forceinline__ float fsqrt_fast(float x) { return x * rsqrtf(x); }

struct Cell { float r, m, E, u, p, q, H; };

__device__ __forceinline__ Cell derive(float r, float m, float E) {
    Cell c;
    float s = rsqrtf(r);      // 1/sqrt(r)
    float ir = s * s;         // ~1/r
    c.r = r; c.m = m; c.E = E;
    c.u = m * ir;
    c.p = 0.4f * (E - 0.5f * m * c.u);
    c.q = r * s;              // sqrt(r)
    c.H = (E + c.p) * ir;
    return c;
}

// Roe flux with Harten entropy fix.
__device__ __forceinline__ float3 roe_flux(const Cell& L, const Cell& R) {
    float rd = __fdividef(1.0f, L.q + R.q);
    float ur = (L.q * L.u + R.q * R.u) * rd;
    float Hr = (L.q * L.H + R.q * R.H) * rd;
    float c2 = fmaxf(0.4f * (Hr - 0.5f * ur * ur), 1e-10f);
    float cinv = rsqrtf(c2);
    float c = c2 * cinv;
    float ic2 = cinv * cinv;
    float e2 = 0.01f * c2;                      // (0.1*c)^2
    float l1 = ur - c, l3 = ur + c;
    float a1 = fsqrt_fast(l1 * l1 + e2);
    float a2 = fsqrt_fast(ur * ur + e2);
    float a3 = fsqrt_fast(l3 * l3 + e2);

    float drho = R.r - L.r, du = R.u - L.u, dp = R.p - L.p;
    float h = 0.5f * ic2;
    float crdu = c * R.r * du;
    float b1 = a1 * ((dp - crdu) * h);
    float b3 = a3 * ((dp + crdu) * h);
    float b2 = a2 * (drho - dp * ic2);
    float uc = ur * c;

    float3 F;
    F.x = 0.5f * (L.m + R.m - (b1 + b2 + b3));
    F.y = 0.5f * ((L.m * L.u + L.p) + (R.m * R.u + R.p)
                  - (b1 * l1 + b2 * ur + b3 * l3));
    F.z = 0.5f * (L.u * (L.E + L.p) + R.u * (R.E + R.p)
                  - (b1 * (Hr - uc) + b2 * (0.5f * ur * ur) + b3 * (Hr + uc)));
    return F;
}

// Block max-reduce of spd, atomicMax into g_maxbits, and last-finishing block
// computes the NEXT step's dt (threadFenceReduction pattern).
__device__ __forceinline__ void reduce_and_dt(float spd, const float* tf) {
    unsigned int bits = __float_as_uint(spd);
    bits = __reduce_max_sync(0xffffffffu, bits);
    __shared__ unsigned int swm[BLK / 32];
    int tid = threadIdx.x;
    if ((tid & 31) == 0) swm[tid >> 5] = bits;
    __syncthreads();
    if (tid == 0) {
        unsigned int m = swm[0];
#pragma unroll
        for (int w = 1; w < BLK / 32; w++) m = max(m, swm[w]);
        atomicMax(&g_maxbits, m);
        __threadfence();
        unsigned int old = atomicAdd(&g_count, 1u);
        if (old == gridDim.x - 1) {
            // All blocks done: their atomicMax results are visible.
            float mx = __uint_as_float(g_maxbits);
            float dt = 5e-4f / mx;                      // CFL*DX / max
            float rem = fmaxf(*tf - g_t, 0.0f);
            dt = fminf(dt, rem);
            g_t += dt;
            g_dtdx = dt * 1000.0f;                      // dt / DX
            g_maxbits = 0u;
            g_count = 0u;
            __threadfence();
        }
    }
}

// Primitives -> conserved, reduce initial max wavespeed, last block computes dt0.
__global__ void __launch_bounds__(BLK) init_kernel(
    const float* __restrict__ rho, const float* __restrict__ u,
    const float* __restrict__ p, const float* __restrict__ tf, int n) {
    int i0 = (blockIdx.x * BLK + threadIdx.x) * 4;
    float4 r4 = *reinterpret_cast<const float4*>(rho + i0);
    float4 u4 = *reinterpret_cast<const float4*>(u + i0);
    float4 p4 = *reinterpret_cast<const float4*>(p + i0);
    float rr[4] = {r4.x, r4.y, r4.z, r4.w};
    float uu[4] = {u4.x, u4.y, u4.z, u4.w};
    float pp[4] = {p4.x, p4.y, p4.z, p4.w};
    float mm[4], ee[4];
    float spd = 0.0f;
#pragma unroll
    for (int k = 0; k < 4; k++) {
        mm[k] = rr[k] * uu[k];
        ee[k] = pp[k] * 2.5f + 0.5f * mm[k] * uu[k];
        float s = rsqrtf(rr[k]);
        float ir = s * s;
        spd = fmaxf(spd, fabsf(uu[k]) + fsqrt_fast(1.4f * pp[k] * ir));
    }
    *reinterpret_cast<float4*>(g_r[0] + i0) = make_float4(rr[0], rr[1], rr[2], rr[3]);
    *reinterpret_cast<float4*>(g_m[0] + i0) = make_float4(mm[0], mm[1], mm[2], mm[3]);
    *reinterpret_cast<float4*>(g_e[0] + i0) = make_float4(ee[0], ee[1], ee[2], ee[3]);
    reduce_and_dt(spd, tf);
}

// One Euler step: 4 cells/thread, fluxes in registers, boundary flux via
// shfl_up (warp interior), shared staging at warp boundaries, recompute at
// block boundary (1 thread per block). Fused new-state max reduction + dt.
template <bool LAST>
__global__ void __launch_bounds__(BLK) flux_kernel(
    int src, float* __restrict__ prim_out, const float* __restrict__ tf, int n) {
    const float* __restrict__ r_in = g_r[src];
    const float* __restrict__ m_in = g_m[src];
    const float* __restrict__ e_in = g_e[src];
    float* __restrict__ r_out = g_r[src ^ 1];
    float* __restrict__ m_out = g_m[src ^ 1];
    float* __restrict__ e_out = g_e[src ^ 1];

    const int tid = threadIdx.x;
    const int lane = tid & 31;
    const int warp = tid >> 5;
    const int i0 = (blockIdx.x * BLK + tid) * 4;

    float4 r4 = *reinterpret_cast<const float4*>(r_in + i0);
    float4 m4 = *reinterpret_cast<const float4*>(m_in + i0);
    float4 e4 = *reinterpret_cast<const float4*>(e_in + i0);
    int iR = min(i0 + 4, n - 1);              // right ghost replicate at domain end

    Cell cell[5];
    cell[0] = derive(r4.x, m4.x, e4.x);
    cell[1] = derive(r4.y, m4.y, e4.y);
    cell[2] = derive(r4.z, m4.z, e4.z);
    cell[3] = derive(r4.w, m4.w, e4.w);
    cell[4] = derive(r_in[iR], m_in[iR], e_in[iR]);

    float3 F[5];
#pragma unroll
    for (int k = 1; k < 5; k++) F[k] = roe_flux(cell[k - 1], cell[k]);

    // Pass F[4] to the right-neighbor thread as its F[0].
    __shared__ float3 s_bound[BLK / 32];
    if (lane == 31) s_bound[warp] = F[4];
    __syncthreads();
    F[0].x = __shfl_up_sync(0xffffffffu, F[4].x, 1);
    F[0].y = __shfl_up_sync(0xffffffffu, F[4].y, 1);
    F[0].z = __shfl_up_sync(0xffffffffu, F[4].z, 1);
    if (lane == 0) {
        if (warp > 0) {
            F[0] = s_bound[warp - 1];
        } else {
            int iL = max(i0 - 1, 0);          // left ghost replicate at domain start
            Cell cl = derive(r_in[iL], m_in[iL], e_in[iL]);
            F[0] = roe_flux(cl, cell[0]);
        }
    }

    const float dtdx = g_dtdx;
    float nr[4], nm[4], ne[4];
#pragma unroll
    for (int k = 0; k < 4; k++) {
        nr[k] = cell[k].r - dtdx * (F[k + 1].x - F[k].x);
        nm[k] = cell[k].m - dtdx * (F[k + 1].y - F[k].y);
        ne[k] = cell[k].E - dtdx * (F[k + 1].z - F[k].z);
    }

    if (LAST) {
        float nu[4], np[4];
#pragma unroll
        for (int k = 0; k < 4; k++) {
            float s = rsqrtf(nr[k]);
            float inr = s * s;
            nu[k] = nm[k] * inr;
            np[k] = 0.4f * (ne[k] - 0.5f * nm[k] * nu[k]);
        }
        *reinterpret_cast<float4*>(prim_out + i0) = make_float4(nr[0], nr[1], nr[2], nr[3]);
        *reinterpret_cast<float4*>(prim_out + n + i0) = make_float4(nu[0], nu[1], nu[2], nu[3]);
        *reinterpret_cast<float4*>(prim_out + 2 * n + i0) = make_float4(np[0], np[1], np[2], np[3]);
    } else {
        *reinterpret_cast<float4*>(r_out + i0) = make_float4(nr[0], nr[1], nr[2], nr[3]);
        *reinterpret_cast<float4*>(m_out + i0) = make_float4(nm[0], nm[1], nm[2], nm[3]);
        *reinterpret_cast<float4*>(e_out + i0) = make_float4(ne[0], ne[1], ne[2], ne[3]);
        float spd = 0.0f;
#pragma unroll
        for (int k = 0; k < 4; k++) {
            float s = rsqrtf(nr[k]);
            float inr = s * s;
            float nu = nm[k] * inr;
            float np = 0.4f * (ne[k] - 0.5f * nm[k] * nu);
            spd = fmaxf(spd, fabsf(nu) + fsqrt_fast(1.4f * np * inr));
        }
        __syncthreads();   // protect s_bound reuse ordering vs swm in reduce
        reduce_and_dt(spd, tf);
    }
}

extern "C" void kernel_launch(void* const* d_in, const int* in_sizes, int n_in,
                              void* d_out, int out_size) {
    const float* rho = (const float*)d_in[0];
    const float* u = (const float*)d_in[1];
    const float* p = (const float*)d_in[2];
    const float* tf = (const float*)d_in[3];
    float* out = (float*)d_out;
    int n = in_sizes[0];
    if (n > NXMAX || (n & 1023)) return;      // expect n = 2^20 (mult of 4*BLK)
    int nblk = n / (4 * BLK);

    pre_kernel<<<1, 1>>>();
    init_kernel<<<nblk, BLK>>>(rho, u, p, tf, n);
    for (int s = 0; s < NSTEPS; s++) {
        if (s < NSTEPS - 1)
            flux_kernel<false><<<nblk, BLK>>>(s & 1, nullptr, tf, n);
        else
            flux_kernel<true><<<nblk, BLK>>>(s & 1, out, tf, n);
    }
}

// round 3
// speedup vs baseline: 1.7536x; 1.0014x over previous
#include <cuda_runtime.h>

#define NXMAX (1 << 20)
#define BLK 256
#define NSTEPS 32

// Double-buffered conserved state (static scratch; no runtime allocation).
__device__ float g_r[2][NXMAX];
__device__ float g_m[2][NXMAX];
__device__ float g_e[2][NXMAX];
__device__ unsigned int g_maxbits;   // running max of |u|+c (positive float bits)
__device__ unsigned int g_count;     // last-block-finish counter
__device__ float g_t;
__device__ float g_dtdx;

__global__ void pre_kernel() {
    g_maxbits = 0u;
    g_count = 0u;
    g_t = 0.0f;
}

// Fast sqrt via single MUFU.RSQ (args are strictly positive here).
__device__ __forceinline__ float fsqrt_fast(float x) { return x * rsqrtf(x); }

struct Cell { float r, m, E, u, p, q, H; };

__device__ __forceinline__ Cell derive(float r, float m, float E) {
    Cell c;
    float s = rsqrtf(r);      // 1/sqrt(r)
    float ir = s * s;         // ~1/r
    c.r = r; c.m = m; c.E = E;
    c.u = m * ir;
    c.p = 0.4f * (E - 0.5f * m * c.u);
    c.q = r * s;              // sqrt(r)
    c.H = (E + c.p) * ir;
    return c;
}

// Roe flux with Harten entropy fix.
__device__ __forceinline__ float3 roe_flux(const Cell& L, const Cell& R) {
    float rd = __fdividef(1.0f, L.q + R.q);
    float ur = (L.q * L.u + R.q * R.u) * rd;
    float Hr = (L.q * L.H + R.q * R.H) * rd;
    float c2 = fmaxf(0.4f * (Hr - 0.5f * ur * ur), 1e-10f);
    float cinv = rsqrtf(c2);
    float c = c2 * cinv;
    float ic2 = cinv * cinv;
    float e2 = 0.01f * c2;                      // (0.1*c)^2
    float l1 = ur - c, l3 = ur + c;
    float a1 = fsqrt_fast(l1 * l1 + e2);
    float a2 = fsqrt_fast(ur * ur + e2);
    float a3 = fsqrt_fast(l3 * l3 + e2);

    float drho = R.r - L.r, du = R.u - L.u, dp = R.p - L.p;
    float h = 0.5f * ic2;
    float crdu = c * R.r * du;
    float b1 = a1 * ((dp - crdu) * h);
    float b3 = a3 * ((dp + crdu) * h);
    float b2 = a2 * (drho - dp * ic2);
    float uc = ur * c;

    float3 F;
    F.x = 0.5f * (L.m + R.m - (b1 + b2 + b3));
    F.y = 0.5f * ((L.m * L.u + L.p) + (R.m * R.u + R.p)
                  - (b1 * l1 + b2 * ur + b3 * l3));
    F.z = 0.5f * (L.u * (L.E + L.p) + R.u * (R.E + R.p)
                  - (b1 * (Hr - uc) + b2 * (0.5f * ur * ur) + b3 * (Hr + uc)));
    return F;
}

// Block max-reduce of spd, atomicMax into g_maxbits, and last-finishing block
// computes the NEXT step's dt (threadFenceReduction pattern).
__device__ __forceinline__ void reduce_and_dt(float spd, const float* tf) {
    unsigned int bits = __float_as_uint(spd);
    bits = __reduce_max_sync(0xffffffffu, bits);
    __shared__ unsigned int swm[BLK / 32];
    int tid = threadIdx.x;
    if ((tid & 31) == 0) swm[tid >> 5] = bits;
    __syncthreads();
    if (tid == 0) {
        unsigned int m = swm[0];
#pragma unroll
        for (int w = 1; w < BLK / 32; w++) m = max(m, swm[w]);
        atomicMax(&g_maxbits, m);
        __threadfence();
        unsigned int old = atomicAdd(&g_count, 1u);
        if (old == gridDim.x - 1) {
            // All blocks done: their atomicMax results are visible.
            float mx = __uint_as_float(g_maxbits);
            float dt = 5e-4f / mx;                      // CFL*DX / max
            float rem = fmaxf(*tf - g_t, 0.0f);
            dt = fminf(dt, rem);
            g_t += dt;
            g_dtdx = dt * 1000.0f;                      // dt / DX
            g_maxbits = 0u;
            g_count = 0u;
            __threadfence();
        }
    }
}

// Primitives -> conserved, reduce initial max wavespeed, last block computes dt0.
__global__ void __launch_bounds__(BLK) init_kernel(
    const float* __restrict__ rho, const float* __restrict__ u,
    const float* __restrict__ p, const float* __restrict__ tf, int n) {
    int i0 = (blockIdx.x * BLK + threadIdx.x) * 4;
    float4 r4 = *reinterpret_cast<const float4*>(rho + i0);
    float4 u4 = *reinterpret_cast<const float4*>(u + i0);
    float4 p4 = *reinterpret_cast<const float4*>(p + i0);
    float rr[4] = {r4.x, r4.y, r4.z, r4.w};
    float uu[4] = {u4.x, u4.y, u4.z, u4.w};
    float pp[4] = {p4.x, p4.y, p4.z, p4.w};
    float mm[4], ee[4];
    float spd = 0.0f;
#pragma unroll
    for (int k = 0; k < 4; k++) {
        mm[k] = rr[k] * uu[k];
        ee[k] = pp[k] * 2.5f + 0.5f * mm[k] * uu[k];
        float s = rsqrtf(rr[k]);
        float ir = s * s;
        spd = fmaxf(spd, fabsf(uu[k]) + fsqrt_fast(1.4f * pp[k] * ir));
    }
    *reinterpret_cast<float4*>(g_r[0] + i0) = make_float4(rr[0], rr[1], rr[2], rr[3]);
    *reinterpret_cast<float4*>(g_m[0] + i0) = make_float4(mm[0], mm[1], mm[2], mm[3]);
    *reinterpret_cast<float4*>(g_e[0] + i0) = make_float4(ee[0], ee[1], ee[2], ee[3]);
    reduce_and_dt(spd, tf);
}

// One Euler step: 4 cells/thread, fluxes in registers, boundary flux via
// shfl_up (warp interior), shared staging at warp boundaries, recompute at
// block boundary (1 thread per block). Fused new-state max reduction + dt.
template <bool LAST>
__global__ void __launch_bounds__(BLK) flux_kernel(
    int src, float* __restrict__ prim_out, const float* __restrict__ tf, int n) {
    const float* __restrict__ r_in = g_r[src];
    const float* __restrict__ m_in = g_m[src];
    const float* __restrict__ e_in = g_e[src];
    float* __restrict__ r_out = g_r[src ^ 1];
    float* __restrict__ m_out = g_m[src ^ 1];
    float* __restrict__ e_out = g_e[src ^ 1];

    const int tid = threadIdx.x;
    const int lane = tid & 31;
    const int warp = tid >> 5;
    const int i0 = (blockIdx.x * BLK + tid) * 4;

    float4 r4 = *reinterpret_cast<const float4*>(r_in + i0);
    float4 m4 = *reinterpret_cast<const float4*>(m_in + i0);
    float4 e4 = *reinterpret_cast<const float4*>(e_in + i0);
    int iR = min(i0 + 4, n - 1);              // right ghost replicate at domain end

    Cell cell[5];
    cell[0] = derive(r4.x, m4.x, e4.x);
    cell[1] = derive(r4.y, m4.y, e4.y);
    cell[2] = derive(r4.z, m4.z, e4.z);
    cell[3] = derive(r4.w, m4.w, e4.w);
    cell[4] = derive(r_in[iR], m_in[iR], e_in[iR]);

    float3 F[5];
#pragma unroll
    for (int k = 1; k < 5; k++) F[k] = roe_flux(cell[k - 1], cell[k]);

    // Pass F[4] to the right-neighbor thread as its F[0].
    __shared__ float3 s_bound[BLK / 32];
    if (lane == 31) s_bound[warp] = F[4];
    __syncthreads();
    F[0].x = __shfl_up_sync(0xffffffffu, F[4].x, 1);
    F[0].y = __shfl_up_sync(0xffffffffu, F[4].y, 1);
    F[0].z = __shfl_up_sync(0xffffffffu, F[4].z, 1);
    if (lane == 0) {
        if (warp > 0) {
            F[0] = s_bound[warp - 1];
        } else {
            int iL = max(i0 - 1, 0);          // left ghost replicate at domain start
            Cell cl = derive(r_in[iL], m_in[iL], e_in[iL]);
            F[0] = roe_flux(cl, cell[0]);
        }
    }

    const float dtdx = g_dtdx;
    float nr[4], nm[4], ne[4];
#pragma unroll
    for (int k = 0; k < 4; k++) {
        nr[k] = cell[k].r - dtdx * (F[k + 1].x - F[k].x);
        nm[k] = cell[k].m - dtdx * (F[k + 1].y - F[k].y);
        ne[k] = cell[k].E - dtdx * (F[k + 1].z - F[k].z);
    }

    if (LAST) {
        float nu[4], np[4];
#pragma unroll
        for (int k = 0; k < 4; k++) {
            float s = rsqrtf(nr[k]);
            float inr = s * s;
            nu[k] = nm[k] * inr;
            np[k] = 0.4f * (ne[k] - 0.5f * nm[k] * nu[k]);
        }
        *reinterpret_cast<float4*>(prim_out + i0) = make_float4(nr[0], nr[1], nr[2], nr[3]);
        *reinterpret_cast<float4*>(prim_out + n + i0) = make_float4(nu[0], nu[1], nu[2], nu[3]);
        *reinterpret_cast<float4*>(prim_out + 2 * n + i0) = make_float4(np[0], np[1], np[2], np[3]);
    } else {
        *reinterpret_cast<float4*>(r_out + i0) = make_float4(nr[0], nr[1], nr[2], nr[3]);
        *reinterpret_cast<float4*>(m_out + i0) = make_float4(nm[0], nm[1], nm[2], nm[3]);
        *reinterpret_cast<float4*>(e_out + i0) = make_float4(ne[0], ne[1], ne[2], ne[3]);
        float spd = 0.0f;
#pragma unroll
        for (int k = 0; k < 4; k++) {
            float s = rsqrtf(nr[k]);
            float inr = s * s;
            float nu = nm[k] * inr;
            float np = 0.4f * (ne[k] - 0.5f * nm[k] * nu);
            spd = fmaxf(spd, fabsf(nu) + fsqrt_fast(1.4f * np * inr));
        }
        __syncthreads();   // protect s_bound reuse ordering vs swm in reduce
        reduce_and_dt(spd, tf);
    }
}

extern "C" void kernel_launch(void* const* d_in, const int* in_sizes, int n_in,
                              void* d_out, int out_size) {
    const float* rho = (const float*)d_in[0];
    const float* u = (const float*)d_in[1];
    const float* p = (const float*)d_in[2];
    const float* tf = (const float*)d_in[3];
    float* out = (float*)d_out;
    int n = in_sizes[0];
    if (n > NXMAX || (n & 1023)) return;      // expect n = 2^20 (mult of 4*BLK)
    int nblk = n / (4 * BLK);

    pre_kernel<<<1, 1>>>();
    init_kernel<<<nblk, BLK>>>(rho, u, p, tf, n);
    for (int s = 0; s < NSTEPS; s++) {
        if (s < NSTEPS - 1)
            flux_kernel<false><<<nblk, BLK>>>(s & 1, nullptr, tf, n);
        else
            flux_kernel<true><<<nblk, BLK>>>(s & 1, out, tf, n);
    }
}

// round 4
// speedup vs baseline: 1.7600x; 1.0036x over previous
#include <cuda_runtime.h>

#define NXMAX (1 << 20)
#define BLK 256
#define NSTEPS 32

// Double-buffered conserved state (static scratch; no runtime allocation).
__device__ float g_r[2][NXMAX];
__device__ float g_m[2][NXMAX];
__device__ float g_e[2][NXMAX];
__device__ unsigned int g_maxbits;   // running max of |u|+c (positive float bits)
__device__ unsigned int g_count;     // last-block-finish counter
__device__ float g_t;
__device__ float g_dtdx;

__global__ void pre_kernel() {
    g_maxbits = 0u;
    g_count = 0u;
    g_t = 0.0f;
}

// Fast sqrt via single MUFU.RSQ (args are strictly positive here).
__device__ __forceinline__ float fsqrt_fast(float x) { return x * rsqrtf(x); }

struct Cell { float r, m, E, u, p, q, H; };

__device__ __forceinline__ Cell derive(float r, float m, float E) {
    Cell c;
    float s = rsqrtf(r);      // 1/sqrt(r)
    float ir = s * s;         // ~1/r
    c.r = r; c.m = m; c.E = E;
    c.u = m * ir;
    c.p = 0.4f * (E - 0.5f * m * c.u);
    c.q = r * s;              // sqrt(r)
    c.H = (E + c.p) * ir;
    return c;
}

// Roe flux with Harten entropy fix.
__device__ __forceinline__ float3 roe_flux(const Cell& L, const Cell& R) {
    float rd = __fdividef(1.0f, L.q + R.q);
    float ur = (L.q * L.u + R.q * R.u) * rd;
    float Hr = (L.q * L.H + R.q * R.H) * rd;
    float c2 = fmaxf(0.4f * (Hr - 0.5f * ur * ur), 1e-10f);
    float cinv = rsqrtf(c2);
    float c = c2 * cinv;
    float ic2 = cinv * cinv;
    float e2 = 0.01f * c2;                      // (0.1*c)^2
    float l1 = ur - c, l3 = ur + c;
    float a1 = fsqrt_fast(l1 * l1 + e2);
    float a2 = fsqrt_fast(ur * ur + e2);
    float a3 = fsqrt_fast(l3 * l3 + e2);

    float drho = R.r - L.r, du = R.u - L.u, dp = R.p - L.p;
    float h = 0.5f * ic2;
    float crdu = c * R.r * du;
    float b1 = a1 * ((dp - crdu) * h);
    float b3 = a3 * ((dp + crdu) * h);
    float b2 = a2 * (drho - dp * ic2);
    float uc = ur * c;

    float3 F;
    F.x = 0.5f * (L.m + R.m - (b1 + b2 + b3));
    F.y = 0.5f * ((L.m * L.u + L.p) + (R.m * R.u + R.p)
                  - (b1 * l1 + b2 * ur + b3 * l3));
    F.z = 0.5f * (L.u * (L.E + L.p) + R.u * (R.E + R.p)
                  - (b1 * (Hr - uc) + b2 * (0.5f * ur * ur) + b3 * (Hr + uc)));
    return F;
}

// Block max-reduce of spd, atomicMax into g_maxbits, and last-finishing block
// computes the NEXT step's dt (threadFenceReduction pattern).
__device__ __forceinline__ void reduce_and_dt(float spd, const float* tf) {
    unsigned int bits = __float_as_uint(spd);
    bits = __reduce_max_sync(0xffffffffu, bits);
    __shared__ unsigned int swm[BLK / 32];
    int tid = threadIdx.x;
    if ((tid & 31) == 0) swm[tid >> 5] = bits;
    __syncthreads();
    if (tid == 0) {
        unsigned int m = swm[0];
#pragma unroll
        for (int w = 1; w < BLK / 32; w++) m = max(m, swm[w]);
        atomicMax(&g_maxbits, m);
        __threadfence();
        unsigned int old = atomicAdd(&g_count, 1u);
        if (old == gridDim.x - 1) {
            // All blocks done: their atomicMax results are visible.
            float mx = __uint_as_float(g_maxbits);
            float dt = 5e-4f / mx;                      // CFL*DX / max
            float rem = fmaxf(*tf - g_t, 0.0f);
            dt = fminf(dt, rem);
            g_t += dt;
            g_dtdx = dt * 1000.0f;                      // dt / DX
            g_maxbits = 0u;
            g_count = 0u;
            __threadfence();
        }
    }
}

// Primitives -> conserved, reduce initial max wavespeed, last block computes dt0.
__global__ void __launch_bounds__(BLK) init_kernel(
    const float* __restrict__ rho, const float* __restrict__ u,
    const float* __restrict__ p, const float* __restrict__ tf, int n) {
    int i0 = (blockIdx.x * BLK + threadIdx.x) * 4;
    float4 r4 = *reinterpret_cast<const float4*>(rho + i0);
    float4 u4 = *reinterpret_cast<const float4*>(u + i0);
    float4 p4 = *reinterpret_cast<const float4*>(p + i0);
    float rr[4] = {r4.x, r4.y, r4.z, r4.w};
    float uu[4] = {u4.x, u4.y, u4.z, u4.w};
    float pp[4] = {p4.x, p4.y, p4.z, p4.w};
    float mm[4], ee[4];
    float spd = 0.0f;
#pragma unroll
    for (int k = 0; k < 4; k++) {
        mm[k] = rr[k] * uu[k];
        ee[k] = pp[k] * 2.5f + 0.5f * mm[k] * uu[k];
        float s = rsqrtf(rr[k]);
        float ir = s * s;
        spd = fmaxf(spd, fabsf(uu[k]) + fsqrt_fast(1.4f * pp[k] * ir));
    }
    *reinterpret_cast<float4*>(g_r[0] + i0) = make_float4(rr[0], rr[1], rr[2], rr[3]);
    *reinterpret_cast<float4*>(g_m[0] + i0) = make_float4(mm[0], mm[1], mm[2], mm[3]);
    *reinterpret_cast<float4*>(g_e[0] + i0) = make_float4(ee[0], ee[1], ee[2], ee[3]);
    reduce_and_dt(spd, tf);
}

// One Euler step: 4 cells/thread, fluxes in registers, boundary flux via
// shfl_up (warp interior), shared staging at warp boundaries, recompute at
// block boundary (1 thread per block). Fused new-state max reduction + dt.
template <bool LAST>
__global__ void __launch_bounds__(BLK) flux_kernel(
    int src, float* __restrict__ prim_out, const float* __restrict__ tf, int n) {
    const float* __restrict__ r_in = g_r[src];
    const float* __restrict__ m_in = g_m[src];
    const float* __restrict__ e_in = g_e[src];
    float* __restrict__ r_out = g_r[src ^ 1];
    float* __restrict__ m_out = g_m[src ^ 1];
    float* __restrict__ e_out = g_e[src ^ 1];

    const int tid = threadIdx.x;
    const int lane = tid & 31;
    const int warp = tid >> 5;
    const int i0 = (blockIdx.x * BLK + tid) * 4;

    float4 r4 = *reinterpret_cast<const float4*>(r_in + i0);
    float4 m4 = *reinterpret_cast<const float4*>(m_in + i0);
    float4 e4 = *reinterpret_cast<const float4*>(e_in + i0);
    int iR = min(i0 + 4, n - 1);              // right ghost replicate at domain end

    Cell cell[5];
    cell[0] = derive(r4.x, m4.x, e4.x);
    cell[1] = derive(r4.y, m4.y, e4.y);
    cell[2] = derive(r4.z, m4.z, e4.z);
    cell[3] = derive(r4.w, m4.w, e4.w);
    cell[4] = derive(r_in[iR], m_in[iR], e_in[iR]);

    float3 F[5];
#pragma unroll
    for (int k = 1; k < 5; k++) F[k] = roe_flux(cell[k - 1], cell[k]);

    // Pass F[4] to the right-neighbor thread as its F[0].
    __shared__ float3 s_bound[BLK / 32];
    if (lane == 31) s_bound[warp] = F[4];
    __syncthreads();
    F[0].x = __shfl_up_sync(0xffffffffu, F[4].x, 1);
    F[0].y = __shfl_up_sync(0xffffffffu, F[4].y, 1);
    F[0].z = __shfl_up_sync(0xffffffffu, F[4].z, 1);
    if (lane == 0) {
        if (warp > 0) {
            F[0] = s_bound[warp - 1];
        } else {
            int iL = max(i0 - 1, 0);          // left ghost replicate at domain start
            Cell cl = derive(r_in[iL], m_in[iL], e_in[iL]);
            F[0] = roe_flux(cl, cell[0]);
        }
    }

    const float dtdx = g_dtdx;
    float nr[4], nm[4], ne[4];
#pragma unroll
    for (int k = 0; k < 4; k++) {
        nr[k] = cell[k].r - dtdx * (F[k + 1].x - F[k].x);
        nm[k] = cell[k].m - dtdx * (F[k + 1].y - F[k].y);
        ne[k] = cell[k].E - dtdx * (F[k + 1].z - F[k].z);
    }

    if (LAST) {
        float nu[4], np[4];
#pragma unroll
        for (int k = 0; k < 4; k++) {
            float s = rsqrtf(nr[k]);
            float inr = s * s;
            nu[k] = nm[k] * inr;
            np[k] = 0.4f * (ne[k] - 0.5f * nm[k] * nu[k]);
        }
        *reinterpret_cast<float4*>(prim_out + i0) = make_float4(nr[0], nr[1], nr[2], nr[3]);
        *reinterpret_cast<float4*>(prim_out + n + i0) = make_float4(nu[0], nu[1], nu[2], nu[3]);
        *reinterpret_cast<float4*>(prim_out + 2 * n + i0) = make_float4(np[0], np[1], np[2], np[3]);
    } else {
        *reinterpret_cast<float4*>(r_out + i0) = make_float4(nr[0], nr[1], nr[2], nr[3]);
        *reinterpret_cast<float4*>(m_out + i0) = make_float4(nm[0], nm[1], nm[2], nm[3]);
        *reinterpret_cast<float4*>(e_out + i0) = make_float4(ne[0], ne[1], ne[2], ne[3]);
        float spd = 0.0f;
#pragma unroll
        for (int k = 0; k < 4; k++) {
            float s = rsqrtf(nr[k]);
            float inr = s * s;
            float nu = nm[k] * inr;
            float np = 0.4f * (ne[k] - 0.5f * nm[k] * nu);
            spd = fmaxf(spd, fabsf(nu) + fsqrt_fast(1.4f * np * inr));
        }
        __syncthreads();   // protect s_bound reuse ordering vs swm in reduce
        reduce_and_dt(spd, tf);
    }
}

extern "C" void kernel_launch(void* const* d_in, const int* in_sizes, int n_in,
                              void* d_out, int out_size) {
    const float* rho = (const float*)d_in[0];
    const float* u = (const float*)d_in[1];
    const float* p = (const float*)d_in[2];
    const float* tf = (const float*)d_in[3];
    float* out = (float*)d_out;
    int n = in_sizes[0];
    if (n > NXMAX || (n & 1023)) return;      // expect n = 2^20 (mult of 4*BLK)
    int nblk = n / (4 * BLK);

    pre_kernel<<<1, 1>>>();
    init_kernel<<<nblk, BLK>>>(rho, u, p, tf, n);
    for (int s = 0; s < NSTEPS; s++) {
        if (s < NSTEPS - 1)
            flux_kernel<false><<<nblk, BLK>>>(s & 1, nullptr, tf, n);
        else
            flux_kernel<true><<<nblk, BLK>>>(s & 1, out, tf, n);
    }
}